// round 8
// baseline (speedup 1.0000x reference)
#include <cuda_runtime.h>
#include <math.h>

#define Bn 4
#define Tt 8
#define Cc 64
#define Ff 16
#define Nn 8192
#define HW 1024      // H*W
#define BN (Bn*Nn)   // 32768

typedef unsigned long long u64;

// Scratch (device globals: no allocations allowed in kernel_launch)
__device__ __align__(16) float g_pooled[BN];
__device__ __align__(16) float g_v[BN];

// ---- packed f32x2 helpers (Blackwell; ptxas never emits FFMA2 from C++) ----
__device__ __forceinline__ u64 f2fma(u64 a, u64 b, u64 c) {
    u64 d;
    asm("fma.rn.f32x2 %0, %1, %2, %3;" : "=l"(d) : "l"(a), "l"(b), "l"(c));
    return d;
}
__device__ __forceinline__ u64 f2add(u64 a, u64 b) {
    u64 d;
    asm("add.rn.f32x2 %0, %1, %2;" : "=l"(d) : "l"(a), "l"(b));
    return d;
}
__device__ __forceinline__ u64 f2mul(u64 a, u64 b) {
    u64 d;
    asm("mul.rn.f32x2 %0, %1, %2;" : "=l"(d) : "l"(a), "l"(b));
    return d;
}
__device__ __forceinline__ u64 f2pack(float lo, float hi) {
    u64 d;
    asm("mov.b64 %0, {%1, %2};" : "=l"(d) : "f"(lo), "f"(hi));
    return d;
}
__device__ __forceinline__ void f2unpack(u64 a, float& lo, float& hi) {
    asm("mov.b64 {%0, %1}, %2;" : "=f"(lo), "=f"(hi) : "l"(a));
}
__device__ __forceinline__ u64 ld64(const float* p) {
    return __double_as_longlong(*reinterpret_cast<const double*>(p));
}
// Streaming 16B load with 256B L2 sector promotion
__device__ __forceinline__ void ldcs256(const void* p, u64& lo, u64& hi) {
    asm("ld.global.cs.L2::256B.v2.u64 {%0, %1}, [%2];"
        : "=l"(lo), "=l"(hi) : "l"(p));
}

// ---------------------------------------------------------------------------
// Kernel 1: pooled[b,n] = wbar . x[b,:,n] + bbar  (conv1 + avgpool collapsed)
// Warp layout: lane = cchunk*8 + q. Each lane: float4 over hw, 16 channels,
// 16 independent loads in flight. Butterfly-reduce over the 4 c-chunks.
// 32768 threads total -> ~8MB in flight (whole tensor).
// ---------------------------------------------------------------------------
__global__ void __launch_bounds__(128) pooled_kernel(
    const float* __restrict__ x,
    const float* __restrict__ conv1_w,
    const float* __restrict__ conv1_b)
{
    __shared__ float swb[Cc];
    __shared__ float sbb;
    int tid = threadIdx.x;
    if (tid < Cc) {
        float s = 0.f;
        #pragma unroll
        for (int f = 0; f < Ff; ++f) s += conv1_w[f * Cc + tid];
        swb[tid] = s * (1.f / Ff);
    }
    if (tid == Cc) {
        float s = 0.f;
        #pragma unroll
        for (int f = 0; f < Ff; ++f) s += conv1_b[f];
        sbb = s * (1.f / Ff);
    }
    __syncthreads();

    int warp = tid >> 5, lane = tid & 31;
    int wg = blockIdx.x * 4 + warp;          // [0, 1024)
    int q = lane & 7, cchunk = lane >> 3;    // 8 hw-quads x 4 c-chunks
    int Q = wg * 8 + q;                      // [0, 8192) hw-quads
    int b  = Q >> 11;                        // 2048 quads per batch
    int r  = Q & 2047;
    int t  = r >> 8;                         // 256 quads per t
    int hw = (r & 255) << 2;

    const float4* xp = (const float4*)(x + (size_t)((b * Tt + t) * Cc + cchunk * 16) * HW + hw);
    const int STRIDE4 = HW / 4;              // 256 float4 per channel row

    float4 xv[16];
    #pragma unroll
    for (int i = 0; i < 16; ++i) xv[i] = xp[i * STRIDE4];

    float ax = 0.f, ay = 0.f, az = 0.f, aw = 0.f;
    #pragma unroll
    for (int i = 0; i < 16; ++i) {
        float wv = swb[cchunk * 16 + i];
        ax = fmaf(wv, xv[i].x, ax);
        ay = fmaf(wv, xv[i].y, ay);
        az = fmaf(wv, xv[i].z, az);
        aw = fmaf(wv, xv[i].w, aw);
    }

    // reduce over c-chunks (lanes xor 8, xor 16)
    #pragma unroll
    for (int off = 8; off <= 16; off <<= 1) {
        ax += __shfl_xor_sync(0xffffffffu, ax, off);
        ay += __shfl_xor_sync(0xffffffffu, ay, off);
        az += __shfl_xor_sync(0xffffffffu, az, off);
        aw += __shfl_xor_sync(0xffffffffu, aw, off);
    }

    if (lane < 8) {
        float4 o = make_float4(ax + sbb, ay + sbb, az + sbb, aw + sbb);
        *reinterpret_cast<float4*>(&g_pooled[b * Nn + t * HW + hw]) = o;
    }
}

// ---------------------------------------------------------------------------
// Kernel 2: v[b,n] = sigmoid(pooled[b,:] . W[n,:] + bias[n])
// Warp: 4 rows x 4 batches. 16 independent 16B streaming loads per lane per
// outer iteration (4 rows x unroll 4) -> 8KB in flight per warp.
// 512 blocks x 128 threads, 3 blocks/SM (reg cap ~168).
// ---------------------------------------------------------------------------
__global__ void __launch_bounds__(128, 3) gemv_kernel(
    const float* __restrict__ Wm,
    const float* __restrict__ bias)
{
    int warp = threadIdx.x >> 5;
    int lane = threadIdx.x & 31;
    int n0 = (blockIdx.x * 4 + warp) * 4;       // first of 4 rows

    const double2* Wv = (const double2*)Wm;     // 16B units
    const double2* Pv = (const double2*)g_pooled;
    const int K4 = Nn / 4;                      // 2048 units per row

    u64 acc[4][4];
    #pragma unroll
    for (int b = 0; b < 4; ++b)
        #pragma unroll
        for (int r = 0; r < 4; ++r) acc[b][r] = 0ull;

    for (int ko = 0; ko < K4; ko += 128) {
        u64 wlo[4][4], whi[4][4];   // [u][r]
        #pragma unroll
        for (int u = 0; u < 4; ++u)
            #pragma unroll
            for (int r = 0; r < 4; ++r)
                ldcs256(Wv + (size_t)(n0 + r) * K4 + ko + u * 32 + lane,
                        wlo[u][r], whi[u][r]);

        #pragma unroll
        for (int u = 0; u < 4; ++u) {
            u64 plo[4], phi[4];
            #pragma unroll
            for (int b = 0; b < 4; ++b) {
                double2 pd = __ldg(Pv + b * K4 + ko + u * 32 + lane);
                plo[b] = __double_as_longlong(pd.x);
                phi[b] = __double_as_longlong(pd.y);
            }
            #pragma unroll
            for (int r = 0; r < 4; ++r)
                #pragma unroll
                for (int b = 0; b < 4; ++b) {
                    acc[b][r] = f2fma(plo[b], wlo[u][r], acc[b][r]);
                    acc[b][r] = f2fma(phi[b], whi[u][r], acc[b][r]);
                }
        }
    }

    // Collapse packed lanes, warp butterfly-reduce 16 scalars
    float red[4][4];
    #pragma unroll
    for (int b = 0; b < 4; ++b)
        #pragma unroll
        for (int r = 0; r < 4; ++r) {
            float lo, hi;
            f2unpack(acc[b][r], lo, hi);
            float v = lo + hi;
            #pragma unroll
            for (int off = 16; off > 0; off >>= 1)
                v += __shfl_xor_sync(0xffffffffu, v, off);
            red[b][r] = v;
        }

    if (lane == 0) {
        #pragma unroll
        for (int r = 0; r < 4; ++r) {
            float bi = bias[n0 + r];
            #pragma unroll
            for (int b = 0; b < 4; ++b) {
                float s = red[b][r] + bi;
                g_v[b * Nn + n0 + r] = 1.f / (1.f + __expf(-s));
            }
        }
    }
}

// ---------------------------------------------------------------------------
// Kernel 3: out[b,t,f,h,w] = v[b,n] * (g3_w @ x + g3_b)[b,n,f]
// One thread = 2 hw; channel loads batched 16-deep for MLP.
// 128 blocks x 128 threads = 16384 threads = BN/2 work items exactly.
// ---------------------------------------------------------------------------
__global__ void __launch_bounds__(128) out_kernel(
    const float* __restrict__ x,
    const float* __restrict__ g3_w,
    const float* __restrict__ g3_b,
    float* __restrict__ out)
{
    __shared__ u64 sw2[Ff * Cc];   // (w,w) packed, 8KB
    __shared__ u64 sb2[Ff];
    for (int i = threadIdx.x; i < Ff * Cc; i += blockDim.x) {
        float w = g3_w[i];
        sw2[i] = f2pack(w, w);
    }
    if (threadIdx.x < Ff) {
        float b = g3_b[threadIdx.x];
        sb2[threadIdx.x] = f2pack(b, b);
    }
    __syncthreads();

    int i2  = blockIdx.x * blockDim.x + threadIdx.x;  // [0, B*N/2)
    int b   = i2 >> 12;
    int j   = i2 & 4095;
    int t   = j >> 9;
    int hw  = (j & 511) << 1;
    const float* xp = x + (size_t)((b * Tt + t) * Cc) * HW + hw;

    u64 acc[Ff];
    #pragma unroll
    for (int f = 0; f < Ff; ++f) acc[f] = 0ull;

    #pragma unroll
    for (int cb = 0; cb < Cc; cb += 16) {
        u64 xv[16];
        #pragma unroll
        for (int i = 0; i < 16; ++i) xv[i] = ld64(xp + (cb + i) * HW);
        #pragma unroll
        for (int i = 0; i < 16; ++i)
            #pragma unroll
            for (int f = 0; f < Ff; ++f)
                acc[f] = f2fma(xv[i], sw2[f * Cc + cb + i], acc[f]);
    }

    u64 v2 = ld64(&g_v[b * Nn + t * HW + hw]);
    float* op = out + (size_t)((b * Tt + t) * Ff) * HW + hw;
    #pragma unroll
    for (int f = 0; f < Ff; ++f) {
        u64 r = f2mul(f2add(acc[f], sb2[f]), v2);
        float lo, hi;
        f2unpack(r, lo, hi);
        *reinterpret_cast<float2*>(op + f * HW) = make_float2(lo, hi);
    }
}

// ---------------------------------------------------------------------------
extern "C" void kernel_launch(void* const* d_in, const int* in_sizes, int n_in,
                              void* d_out, int out_size)
{
    const float* x       = (const float*)d_in[0];
    // d_in[1] = x1 (unused by reference)
    const float* conv1_w = (const float*)d_in[2];
    const float* conv1_b = (const float*)d_in[3];
    const float* g3_w    = (const float*)d_in[4];
    const float* g3_b    = (const float*)d_in[5];
    const float* ffnn1_w = (const float*)d_in[6];
    const float* ffnn1_b = (const float*)d_in[7];
    float* out = (float*)d_out;

    pooled_kernel<<<256, 128>>>(x, conv1_w, conv1_b);       // 1024 warps
    gemv_kernel<<<512, 128>>>(ffnn1_w, ffnn1_b);            // 2048 warps, 4 rows each
    out_kernel<<<BN / 2 / 128, 128>>>(x, g3_w, g3_b, out);  // 16384 threads (2 hw each)
}

// round 9
// speedup vs baseline: 1.1984x; 1.1984x over previous
#include <cuda_runtime.h>
#include <math.h>

#define Bn 4
#define Tt 8
#define Cc 64
#define Ff 16
#define Nn 8192
#define HW 1024      // H*W
#define BN (Bn*Nn)   // 32768
#define KC4 128      // K-chunk in float4 units (512 floats)
#define NCH (Nn/4/KC4)  // 16 chunks

typedef unsigned long long u64;

// Scratch (device globals: no allocations allowed in kernel_launch)
__device__ __align__(16) float g_pooled[BN];
__device__ __align__(16) float g_v[BN];

// ---- packed f32x2 helpers (Blackwell; ptxas never emits FFMA2 from C++) ----
__device__ __forceinline__ u64 f2fma(u64 a, u64 b, u64 c) {
    u64 d;
    asm("fma.rn.f32x2 %0, %1, %2, %3;" : "=l"(d) : "l"(a), "l"(b), "l"(c));
    return d;
}
__device__ __forceinline__ u64 f2add(u64 a, u64 b) {
    u64 d;
    asm("add.rn.f32x2 %0, %1, %2;" : "=l"(d) : "l"(a), "l"(b));
    return d;
}
__device__ __forceinline__ u64 f2mul(u64 a, u64 b) {
    u64 d;
    asm("mul.rn.f32x2 %0, %1, %2;" : "=l"(d) : "l"(a), "l"(b));
    return d;
}
__device__ __forceinline__ u64 f2pack(float lo, float hi) {
    u64 d;
    asm("mov.b64 %0, {%1, %2};" : "=l"(d) : "f"(lo), "f"(hi));
    return d;
}
__device__ __forceinline__ void f2unpack(u64 a, float& lo, float& hi) {
    asm("mov.b64 {%0, %1}, %2;" : "=f"(lo), "=f"(hi) : "l"(a));
}
__device__ __forceinline__ u64 ld64(const float* p) {
    return __double_as_longlong(*reinterpret_cast<const double*>(p));
}
// Streaming 16B load with 256B L2 sector promotion
__device__ __forceinline__ void ldcs256(const void* p, u64& lo, u64& hi) {
    asm("ld.global.cs.L2::256B.v2.u64 {%0, %1}, [%2];"
        : "=l"(lo), "=l"(hi) : "l"(p));
}

// ---------------------------------------------------------------------------
// Kernel 1: pooled[b,n] = wbar . x[b,:,n] + bbar  (conv1 + avgpool collapsed)
// Lane = cgroup*4 + quad: 8 channel-groups x 4 hw-quads per warp.
// Each lane: 8 independent float4 loads (fits in regs -> real 8-deep MLP).
// 65536 threads -> whole 8MB tensor in flight.
// ---------------------------------------------------------------------------
__global__ void pooled_kernel(
    const float* __restrict__ x,
    const float* __restrict__ conv1_w,
    const float* __restrict__ conv1_b)
{
    __shared__ float swb[Cc];
    __shared__ float sbb;
    int tid = threadIdx.x;
    if (tid < Cc) {
        float s = 0.f;
        #pragma unroll
        for (int f = 0; f < Ff; ++f) s += conv1_w[f * Cc + tid];
        swb[tid] = s * (1.f / Ff);
    }
    if (tid == Cc) {
        float s = 0.f;
        #pragma unroll
        for (int f = 0; f < Ff; ++f) s += conv1_b[f];
        sbb = s * (1.f / Ff);
    }
    __syncthreads();

    int warp = tid >> 5, lane = tid & 31;
    int wg = blockIdx.x * 4 + warp;          // [0, 2048)
    int q = lane & 3, cg = lane >> 2;        // 4 hw-quads x 8 c-groups
    int Q = wg * 4 + q;                      // [0, 8192) hw-quads
    int b  = Q >> 11;
    int r  = Q & 2047;
    int t  = r >> 8;
    int hw = (r & 255) << 2;

    const float4* xp = (const float4*)(x + (size_t)((b * Tt + t) * Cc + cg * 8) * HW + hw);
    const int STRIDE4 = HW / 4;

    float4 xv[8];
    #pragma unroll
    for (int i = 0; i < 8; ++i) xv[i] = xp[i * STRIDE4];

    float ax = 0.f, ay = 0.f, az = 0.f, aw = 0.f;
    #pragma unroll
    for (int i = 0; i < 8; ++i) {
        float wv = swb[cg * 8 + i];
        ax = fmaf(wv, xv[i].x, ax);
        ay = fmaf(wv, xv[i].y, ay);
        az = fmaf(wv, xv[i].z, az);
        aw = fmaf(wv, xv[i].w, aw);
    }

    // reduce over c-groups (lane bits [2:5))
    #pragma unroll
    for (int off = 4; off <= 16; off <<= 1) {
        ax += __shfl_xor_sync(0xffffffffu, ax, off);
        ay += __shfl_xor_sync(0xffffffffu, ay, off);
        az += __shfl_xor_sync(0xffffffffu, az, off);
        aw += __shfl_xor_sync(0xffffffffu, aw, off);
    }

    if (lane < 4) {
        float4 o = make_float4(ax + sbb, ay + sbb, az + sbb, aw + sbb);
        *reinterpret_cast<float4*>(&g_pooled[b * Nn + t * HW + hw]) = o;
    }
}

// ---------------------------------------------------------------------------
// Kernel 2: v[b,n] = sigmoid(pooled[b,:] . W[n,:] + bias[n])
// Pooled staged through double-buffered SMEM (loaded once per block per chunk
// instead of per warp) -> L2 traffic drops from 512MB to ~320MB -> HBM-bound.
// 512 blocks x 128 thr, warp = 4 rows, block = 16 rows.
// ---------------------------------------------------------------------------
__global__ void __launch_bounds__(128, 4) gemv_kernel(
    const float* __restrict__ Wm,
    const float* __restrict__ bias)
{
    __shared__ float4 spool[2][Bn][KC4];   // 16 KB
    int tid  = threadIdx.x;
    int warp = tid >> 5;
    int lane = tid & 31;
    int n0 = blockIdx.x * 16 + warp * 4;   // first of 4 rows

    const double2* Wv = (const double2*)Wm;     // 16B units; 2048 per row
    const float4* Pv = (const float4*)g_pooled; // 2048 per batch

    // preload chunk 0
    #pragma unroll
    for (int r = 0; r < 4; ++r) {
        int idx = tid + r * 128;           // 0..511
        int b = idx >> 7, k = idx & 127;
        spool[0][b][k] = __ldg(Pv + (size_t)b * 2048 + k);
    }
    __syncthreads();

    u64 acc[4][4];
    #pragma unroll
    for (int b = 0; b < 4; ++b)
        #pragma unroll
        for (int r = 0; r < 4; ++r) acc[b][r] = 0ull;

    for (int ch = 0; ch < NCH; ++ch) {
        // prefetch next pooled chunk into regs (latency hidden by FMAs below)
        float4 tmp[4];
        if (ch + 1 < NCH) {
            #pragma unroll
            for (int r = 0; r < 4; ++r) {
                int idx = tid + r * 128;
                int b = idx >> 7, k = idx & 127;
                tmp[r] = __ldg(Pv + (size_t)b * 2048 + (ch + 1) * KC4 + k);
            }
        }

        // consume current chunk from smem
        int buf = ch & 1;
        #pragma unroll
        for (int u = 0; u < 4; ++u) {
            int k = u * 32 + lane;          // 0..127 within chunk
            u64 wlo[4], whi[4];
            #pragma unroll
            for (int r = 0; r < 4; ++r)
                ldcs256(Wv + (size_t)(n0 + r) * 2048 + ch * KC4 + k, wlo[r], whi[r]);
            #pragma unroll
            for (int b = 0; b < 4; ++b) {
                ulonglong2 p = *reinterpret_cast<const ulonglong2*>(&spool[buf][b][k]);
                #pragma unroll
                for (int r = 0; r < 4; ++r) {
                    acc[b][r] = f2fma(p.x, wlo[r], acc[b][r]);
                    acc[b][r] = f2fma(p.y, whi[r], acc[b][r]);
                }
            }
        }

        // commit prefetched chunk to the other buffer
        if (ch + 1 < NCH) {
            #pragma unroll
            for (int r = 0; r < 4; ++r) {
                int idx = tid + r * 128;
                int b = idx >> 7, k = idx & 127;
                spool[(ch + 1) & 1][b][k] = tmp[r];
            }
        }
        __syncthreads();
    }

    // Collapse packed lanes, warp butterfly-reduce 16 scalars
    float red[4][4];
    #pragma unroll
    for (int b = 0; b < 4; ++b)
        #pragma unroll
        for (int r = 0; r < 4; ++r) {
            float lo, hi;
            f2unpack(acc[b][r], lo, hi);
            float v = lo + hi;
            #pragma unroll
            for (int off = 16; off > 0; off >>= 1)
                v += __shfl_xor_sync(0xffffffffu, v, off);
            red[b][r] = v;
        }

    if (lane == 0) {
        #pragma unroll
        for (int r = 0; r < 4; ++r) {
            float bi = bias[n0 + r];
            #pragma unroll
            for (int b = 0; b < 4; ++b) {
                float s = red[b][r] + bi;
                g_v[b * Nn + n0 + r] = 1.f / (1.f + __expf(-s));
            }
        }
    }
}

// ---------------------------------------------------------------------------
// Kernel 3: out[b,t,f,h,w] = v[b,n] * (g3_w @ x + g3_b)[b,n,f]
// One thread = 2 hw; channel loads batched 16-deep for MLP.
// ---------------------------------------------------------------------------
__global__ void __launch_bounds__(128) out_kernel(
    const float* __restrict__ x,
    const float* __restrict__ g3_w,
    const float* __restrict__ g3_b,
    float* __restrict__ out)
{
    __shared__ u64 sw2[Ff * Cc];   // (w,w) packed, 8KB
    __shared__ u64 sb2[Ff];
    for (int i = threadIdx.x; i < Ff * Cc; i += blockDim.x) {
        float w = g3_w[i];
        sw2[i] = f2pack(w, w);
    }
    if (threadIdx.x < Ff) {
        float b = g3_b[threadIdx.x];
        sb2[threadIdx.x] = f2pack(b, b);
    }
    __syncthreads();

    int i2  = blockIdx.x * blockDim.x + threadIdx.x;  // [0, B*N/2)
    int b   = i2 >> 12;
    int j   = i2 & 4095;
    int t   = j >> 9;
    int hw  = (j & 511) << 1;
    const float* xp = x + (size_t)((b * Tt + t) * Cc) * HW + hw;

    u64 acc[Ff];
    #pragma unroll
    for (int f = 0; f < Ff; ++f) acc[f] = 0ull;

    #pragma unroll
    for (int cb = 0; cb < Cc; cb += 16) {
        u64 xv[16];
        #pragma unroll
        for (int i = 0; i < 16; ++i) xv[i] = ld64(xp + (cb + i) * HW);
        #pragma unroll
        for (int i = 0; i < 16; ++i)
            #pragma unroll
            for (int f = 0; f < Ff; ++f)
                acc[f] = f2fma(xv[i], sw2[f * Cc + cb + i], acc[f]);
    }

    u64 v2 = ld64(&g_v[b * Nn + t * HW + hw]);
    float* op = out + (size_t)((b * Tt + t) * Ff) * HW + hw;
    #pragma unroll
    for (int f = 0; f < Ff; ++f) {
        u64 r = f2mul(f2add(acc[f], sb2[f]), v2);
        float lo, hi;
        f2unpack(r, lo, hi);
        *reinterpret_cast<float2*>(op + f * HW) = make_float2(lo, hi);
    }
}

// ---------------------------------------------------------------------------
extern "C" void kernel_launch(void* const* d_in, const int* in_sizes, int n_in,
                              void* d_out, int out_size)
{
    const float* x       = (const float*)d_in[0];
    // d_in[1] = x1 (unused by reference)
    const float* conv1_w = (const float*)d_in[2];
    const float* conv1_b = (const float*)d_in[3];
    const float* g3_w    = (const float*)d_in[4];
    const float* g3_b    = (const float*)d_in[5];
    const float* ffnn1_w = (const float*)d_in[6];
    const float* ffnn1_b = (const float*)d_in[7];
    float* out = (float*)d_out;

    pooled_kernel<<<512, 128>>>(x, conv1_w, conv1_b);       // 65536 threads
    gemv_kernel<<<512, 128>>>(ffnn1_w, ffnn1_b);            // 16 rows/block
    out_kernel<<<BN / 2 / 128, 128>>>(x, g3_w, g3_b, out);  // 16384 threads
}